// round 10
// baseline (speedup 1.0000x reference)
#include <cuda_runtime.h>
#include <cuda_bf16.h>
#include <math.h>
#include <stdint.h>

#define BATCH 1024
#define NMAXN 100
#define HD    768

// ---------------- scratch (no allocations allowed) ----------------
__device__ float g_sim[BATCH * 256];
__device__ float g_h  [BATCH * 1152];
__device__ float g_h1 [BATCH * 576];
__device__ unsigned g_counter;
// Ww in bf16 fragment layout for m16n8k16: [kt(24)][nt(16)][lane(32)][reg(4)] (uint32 = bf16x2)
__device__ __align__(16) uint32_t g_WfragB[24 * 16 * 32 * 4];
// W1 in bf16 fragment layout for m16n8k16: [kt(36)][nt(72)][lane(32)][reg(4)]
__device__ __align__(16) uint32_t g_W1fragB[36 * 72 * 32 * 4];

__device__ __forceinline__ uint32_t pack_bf2(float lo, float hi) {
    __nv_bfloat162 p = __float22bfloat162_rn(make_float2(lo, hi));
    return *(uint32_t*)&p;
}
__device__ __forceinline__ void pref_l2(const void* p) {
    asm volatile("prefetch.global.L2 [%0];" :: "l"(p));
}

__device__ __forceinline__ void mma_bf16(float* c, const uint32_t* a, uint32_t b0, uint32_t b1) {
    asm volatile(
        "mma.sync.aligned.m16n8k16.row.col.f32.bf16.bf16.f32 "
        "{%0,%1,%2,%3}, {%4,%5,%6,%7}, {%8,%9}, {%0,%1,%2,%3};"
        : "+f"(c[0]), "+f"(c[1]), "+f"(c[2]), "+f"(c[3])
        : "r"(a[0]), "r"(a[1]), "r"(a[2]), "r"(a[3]), "r"(b0), "r"(b1));
}

// ---------------------------------------------------------------------------
// prep_kernel: counter reset + Ww bf16 frags + W1 bf16 frags in ONE launch
// ---------------------------------------------------------------------------
__global__ void prep_kernel(const float* __restrict__ Ww, const float* __restrict__ W1)
{
    if (blockIdx.x == 0 && threadIdx.x == 0) g_counter = 0u;
    if (blockIdx.x < 192) {
        int idx = blockIdx.x * 256 + threadIdx.x;      // 0..49151
        int r    = idx & 3;
        int lane = (idx >> 2) & 31;
        int nt   = (idx >> 7) & 15;
        int kt   = idx >> 11;
        int g = lane >> 2, tig = lane & 3;
        int n = nt * 8 + g;
        int k = kt * 32 + ((r >> 1) << 4) + ((r & 1) << 3) + 2 * tig;
        g_WfragB[idx] = pack_bf2(Ww[k * 128 + n], Ww[(k + 1) * 128 + n]);
    } else {
        int idx = (blockIdx.x - 192) * 256 + threadIdx.x;   // 0..331775
        int r    = idx & 3;
        int lane = (idx >> 2) & 31;
        int nt   = (idx >> 7) % 72;
        int kt   = idx / 9216;
        int g = lane >> 2, tig = lane & 3;
        int n = nt * 8 + g;
        int k = kt * 32 + ((r >> 1) << 4) + ((r & 1) << 3) + 2 * tig;
        g_W1fragB[idx] = pack_bf2(W1[k * 576 + n], W1[(k + 1) * 576 + n]);
    }
}

// ---------------------------------------------------------------------------
// side_kernel: persistent; per (b,side): bf16 MMA [node;neigh]@Ww, attention.
// R8 mainloop; ctx computed from accumulator registers (no sWng smem at all).
// grid 296, block 256 (8 warps), static smem only (~17 KB)
// ---------------------------------------------------------------------------
__global__ void __launch_bounds__(256, 2) side_kernel(
    const float* __restrict__ node1, const float* __restrict__ node2,
    const float* __restrict__ neigh1, const float* __restrict__ neigh2,
    const float* __restrict__ dist1, const float* __restrict__ dist2,
    const int* __restrict__ len1, const int* __restrict__ len2,
    const float* __restrict__ bw,
    const float* __restrict__ Wa, const float* __restrict__ ba,
    const float* __restrict__ Wdb, const float* __restrict__ bdb)
{
    __shared__ uint32_t sAb[2 * 1792];   // [buf][mt(7)][ks(2)][lane(32)][reg(4)]
    __shared__ float sWa[256], sBw[128], sWn[128];
    __shared__ float sDist[NMAXN], sRaw[NMAXN], sAtt[NMAXN];
    __shared__ float sC0;
    __shared__ int sIdx;

    const int tid  = threadIdx.x;
    const int warp = tid >> 5, lane = tid & 31;
    const int gid  = lane >> 2, tig = lane & 3;

    sWa[tid] = Wa[tid];
    if (tid < 128) sBw[tid] = bw[tid];

    const float bav = ba[0], wdbv = Wdb[0], bdbv = bdb[0];

    while (true) {
        __syncthreads();
        if (tid == 0) sIdx = (int)atomicAdd(&g_counter, 1u);
        __syncthreads();
        const int item = sIdx;
        if (item >= 2 * BATCH) break;
        const int b = item >> 1, side = item & 1;

        const float* node  = side ? node2  : node1;
        const float* neigh = side ? neigh2 : neigh1;
        const float* dist  = side ? dist2  : dist1;
        int len = side ? len2[b] : len1[b];
        if (len < 1) len = 1; if (len > NMAXN) len = NMAXN;
        const int M = len + 1;
        const int mcount = (M + 15) >> 4;

        if (tid < NMAXN) { sDist[tid] = dist[(size_t)b * NMAXN + tid]; sRaw[tid] = 0.f; }
        if (tid == 128) sC0 = 0.f;

        const float* nodeRow   = node  + (size_t)b * HD;
        const float* neighBase = neigh + (size_t)b * NMAXN * HD;

        // L2 prefetch of the whole item (neigh block is contiguous)
        {
            const char* pnb = (const char*)neighBase;
            const int pbytes = len * (HD * 4);
            for (int off = tid * 128; off < pbytes; off += 256 * 128) pref_l2(pnb + off);
            if (tid < 24) pref_l2((const char*)nodeRow + tid * 128);
        }

        int nact = 0;
        const float* srcp[4];
        int sbase[4];
#pragma unroll
        for (int i = 0; i < 4; ++i) {
            int f = tid + i * 256;
            if (f < M * 8) {
                int r = f >> 3, j = f & 7;
                int mt = r >> 4, r16 = r & 15, g8 = r16 & 7, hib = r16 >> 3;
                int ks = j >> 2, half = (j >> 1) & 1, tg = (j & 1) * 2;
                srcp[i]  = (r == 0 ? nodeRow : neighBase + (size_t)(r - 1) * HD) + j * 4;
                sbase[i] = ((mt * 2 + ks) * 32 + g8 * 4 + tg) * 4 + half * 2 + hib;
                nact = i + 1;
            }
        }

        float acc[7][2][4];
#pragma unroll
        for (int mt = 0; mt < 7; ++mt)
#pragma unroll
            for (int ni = 0; ni < 2; ++ni)
#pragma unroll
                for (int q = 0; q < 4; ++q) acc[mt][ni][q] = 0.f;

        // ---- prologue ----
        float4 v[4];
#pragma unroll
        for (int i = 0; i < 4; ++i) if (i < nact) v[i] = *(const float4*)(srcp[i]);

        uint4 bq0 = *(const uint4*)(g_WfragB + ((2 * warp)     * 32 + lane) * 4);
        uint4 bq1 = *(const uint4*)(g_WfragB + ((2 * warp + 1) * 32 + lane) * 4);

#pragma unroll
        for (int i = 0; i < 4; ++i) {
            if (i < nact) {
                sAb[sbase[i]]     = pack_bf2(v[i].x, v[i].y);
                sAb[sbase[i] + 4] = pack_bf2(v[i].z, v[i].w);
            }
        }
#pragma unroll
        for (int i = 0; i < 4; ++i)
            if (i < nact) v[i] = *(const float4*)(srcp[i] + 32);
        __syncthreads();

        // ---- mainloop: 1 barrier per k-tile ----
        for (int kt = 0; kt < 24; ++kt) {
            const uint32_t* cur = sAb + (kt & 1) * 1792;
            uint32_t* nxt = sAb + ((kt + 1) & 1) * 1792;

            uint4 nb0, nb1;
            if (kt < 23) {
                nb0 = *(const uint4*)(g_WfragB + (((kt + 1) * 16 + 2 * warp)     * 32 + lane) * 4);
                nb1 = *(const uint4*)(g_WfragB + (((kt + 1) * 16 + 2 * warp + 1) * 32 + lane) * 4);
#pragma unroll
                for (int i = 0; i < 4; ++i) {
                    if (i < nact) {
                        nxt[sbase[i]]     = pack_bf2(v[i].x, v[i].y);
                        nxt[sbase[i] + 4] = pack_bf2(v[i].z, v[i].w);
                    }
                }
                if (kt < 22) {
#pragma unroll
                    for (int i = 0; i < 4; ++i)
                        if (i < nact) v[i] = *(const float4*)(srcp[i] + (kt + 2) * 32);
                }
            }

            const uint32_t* p0 = (const uint32_t*)&bq0;
            const uint32_t* p1 = (const uint32_t*)&bq1;
#pragma unroll
            for (int ks = 0; ks < 2; ++ks) {
#pragma unroll
                for (int mt = 0; mt < 7; ++mt) {
                    if (mt >= mcount) break;
                    uint4 av = *(const uint4*)(cur + ((mt * 2 + ks) * 32 + lane) * 4);
                    const uint32_t* a = (const uint32_t*)&av;
                    mma_bf16(acc[mt][0], a, p0[2 * ks], p0[2 * ks + 1]);
                    mma_bf16(acc[mt][1], a, p1[2 * ks], p1[2 * ks + 1]);
                }
            }
            if (kt < 23) { bq0 = nb0; bq1 = nb1; }
            __syncthreads();
        }

        // ---- epilogue: bias into acc (wng in regs), fused dots via atomics ----
#pragma unroll
        for (int mt = 0; mt < 7; ++mt) {
            if (mt >= mcount) break;
            int r0 = mt * 16 + gid, r1 = r0 + 8;
            float pr0 = 0.f, pr1 = 0.f;
#pragma unroll
            for (int ni = 0; ni < 2; ++ni) {
                int cc = (2 * warp + ni) * 8 + tig * 2;
                float a0 = acc[mt][ni][0] + sBw[cc];
                float a1 = acc[mt][ni][1] + sBw[cc + 1];
                float a2 = acc[mt][ni][2] + sBw[cc];
                float a3 = acc[mt][ni][3] + sBw[cc + 1];
                acc[mt][ni][0] = a0; acc[mt][ni][1] = a1;
                acc[mt][ni][2] = a2; acc[mt][ni][3] = a3;
                if (r0 == 0) {
                    sWn[cc] = a0; sWn[cc + 1] = a1;
                    pr0 += a0 * sWa[cc] + a1 * sWa[cc + 1];
                } else {
                    pr0 += a0 * sWa[128 + cc] + a1 * sWa[128 + cc + 1];
                }
                pr1 += a2 * sWa[128 + cc] + a3 * sWa[128 + cc + 1];
            }
            pr0 += __shfl_xor_sync(0xffffffffu, pr0, 1);
            pr0 += __shfl_xor_sync(0xffffffffu, pr0, 2);
            pr1 += __shfl_xor_sync(0xffffffffu, pr1, 1);
            pr1 += __shfl_xor_sync(0xffffffffu, pr1, 2);
            if (tig == 0) {
                if (r0 < M) {
                    if (r0 == 0) atomicAdd(&sC0, pr0);
                    else         atomicAdd(&sRaw[r0 - 1], pr0);
                }
                if (r1 < M) atomicAdd(&sRaw[r1 - 1], pr1);
            }
        }
        __syncthreads();

        // ---- softmax over neighbors (warp 0) ----
        if (warp == 0) {
            float cst = sC0 + bav;
            float sc[4], ev[4];
            float mx = -3.4e38f;
#pragma unroll
            for (int q = 0; q < 4; ++q) {
                int n = lane + 32 * q;
                float vv = -3.4e38f;
                if (n < len) {
                    float x = cst + sRaw[n];
                    x = (x > 0.f) ? x : 0.01f * x;
                    vv = x + sDist[n] * wdbv + bdbv;
                }
                sc[q] = vv; mx = fmaxf(mx, vv);
            }
#pragma unroll
            for (int o = 16; o > 0; o >>= 1) mx = fmaxf(mx, __shfl_xor_sync(0xffffffffu, mx, o));
            float s = 0.f;
#pragma unroll
            for (int q = 0; q < 4; ++q) {
                int n = lane + 32 * q;
                float e = (n < len) ? expf(sc[q] - mx) : 0.f;
                ev[q] = e; s += e;
            }
#pragma unroll
            for (int o = 16; o > 0; o >>= 1) s += __shfl_xor_sync(0xffffffffu, s, o);
            float inv = 1.f / s;
#pragma unroll
            for (int q = 0; q < 4; ++q) {
                int n = lane + 32 * q;
                if (n < NMAXN) sAtt[n] = ev[q] * inv;
            }
        }
        __syncthreads();

        // ---- ctx from registers: weight rows by att, butterfly over gid ----
        {
            float c0 = 0.f, c1 = 0.f, c2 = 0.f, c3 = 0.f;
#pragma unroll
            for (int mt = 0; mt < 7; ++mt) {
                if (mt >= mcount) break;
                int r0 = mt * 16 + gid, r1 = r0 + 8;
                float w0 = (r0 >= 1 && r0 <= len) ? sAtt[r0 - 1] : 0.f;
                float w1 = (r1 <= len) ? sAtt[r1 - 1] : 0.f;
                c0 += w0 * acc[mt][0][0] + w1 * acc[mt][0][2];
                c1 += w0 * acc[mt][0][1] + w1 * acc[mt][0][3];
                c2 += w0 * acc[mt][1][0] + w1 * acc[mt][1][2];
                c3 += w0 * acc[mt][1][1] + w1 * acc[mt][1][3];
            }
#pragma unroll
            for (int o = 4; o <= 16; o <<= 1) {
                c0 += __shfl_xor_sync(0xffffffffu, c0, o);
                c1 += __shfl_xor_sync(0xffffffffu, c1, o);
                c2 += __shfl_xor_sync(0xffffffffu, c2, o);
                c3 += __shfl_xor_sync(0xffffffffu, c3, o);
            }
            if (gid == 0) {
                int cc0 = (2 * warp) * 8 + tig * 2;
                int cc1 = (2 * warp + 1) * 8 + tig * 2;
                float* dst = g_sim + (size_t)b * 256 + side * 128;
                float2 o0 = { c0 * sWn[cc0], c1 * sWn[cc0 + 1] };
                float2 o1 = { c2 * sWn[cc1], c3 * sWn[cc1 + 1] };
                *(float2*)(dst + cc0) = o0;
                *(float2*)(dst + cc1) = o1;
            }
        }
    }
}

// ---------------------------------------------------------------------------
// xbuild: xneigh = relu([sim1,sim2]) @ Wn + bn -> g_h[:,896:1152],
// plus pooled/coord into g_h[:,0:896].  grid 256 (4 rows/block)
// ---------------------------------------------------------------------------
__global__ void __launch_bounds__(256) xbuild_kernel(
    const float* __restrict__ Wn, const float* __restrict__ bn,
    const float* __restrict__ pooled, const float* __restrict__ x_coord,
    const float* __restrict__ Wc, const float* __restrict__ bc)
{
    __shared__ float sS[4 * 256];
    const int b0 = blockIdx.x * 4;
    const int tid = threadIdx.x;
#pragma unroll
    for (int r = 0; r < 4; ++r)
        sS[r * 256 + tid] = fmaxf(g_sim[(size_t)(b0 + r) * 256 + tid], 0.f);
    __syncthreads();
    float acc[4];
    const float bnv = bn[tid];
#pragma unroll
    for (int r = 0; r < 4; ++r) acc[r] = bnv;
    for (int k0 = 0; k0 < 256; k0 += 4) {
        float w0 = Wn[(k0 + 0) * 256 + tid];
        float w1 = Wn[(k0 + 1) * 256 + tid];
        float w2 = Wn[(k0 + 2) * 256 + tid];
        float w3 = Wn[(k0 + 3) * 256 + tid];
#pragma unroll
        for (int r = 0; r < 4; ++r) {
            acc[r] += sS[r * 256 + k0] * w0;
            acc[r] += sS[r * 256 + k0 + 1] * w1;
            acc[r] += sS[r * 256 + k0 + 2] * w2;
            acc[r] += sS[r * 256 + k0 + 3] * w3;
        }
    }
#pragma unroll
    for (int r = 0; r < 4; ++r) {
        int b = b0 + r;
        g_h[(size_t)b * 1152 + 896 + tid] = acc[r];
#pragma unroll
        for (int p = 0; p < 3; ++p)
            g_h[(size_t)b * 1152 + p * 256 + tid] = pooled[(size_t)b * 768 + p * 256 + tid];
        if (tid < 128) {
            g_h[(size_t)b * 1152 + 768 + tid] = x_coord[b] * Wc[tid] + bc[tid];
        }
    }
}

// ---------------------------------------------------------------------------
// head_mm: g_h1 = gelu(g_h @ W1 + b1)  bf16, grid (64,9) = 16x64 tiles
// ---------------------------------------------------------------------------
__global__ void __launch_bounds__(256) head_mm_kernel(const float* __restrict__ b1)
{
    __shared__ uint32_t sAb[2 * 256];   // [buf][ks(2)][lane(32)][reg(4)]

    const int tid  = threadIdx.x;
    const int warp = tid >> 5, lane = tid & 31;
    const int gid  = lane >> 2, tig = lane & 3;
    const int m0   = blockIdx.x * 16;
    const int ntg  = blockIdx.y * 8 + warp;

    {
        const char* ph = (const char*)(g_h + (size_t)m0 * 1152);
        for (int off = tid * 128; off < 16 * 1152 * 4; off += 256 * 128) pref_l2(ph + off);
    }

    const bool active = tid < 128;
    const float* srcp = g_h;
    int sbase = 0;
    if (active) {
        int r = tid >> 3, j = tid & 7;
        int g8 = (r & 15) & 7, hib = (r & 15) >> 3;
        int ks = j >> 2, half = (j >> 1) & 1, tg = (j & 1) * 2;
        srcp  = g_h + (size_t)(m0 + r) * 1152 + j * 4;
        sbase = (ks * 32 + g8 * 4 + tg) * 4 + half * 2 + hib;
    }

    float acc[4];
#pragma unroll
    for (int q = 0; q < 4; ++q) acc[q] = 0.f;

    float4 v = make_float4(0.f, 0.f, 0.f, 0.f);
    if (active) {
        v = *(const float4*)(srcp);
        sAb[sbase]     = pack_bf2(v.x, v.y);
        sAb[sbase + 4] = pack_bf2(v.z, v.w);
        v = *(const float4*)(srcp + 32);
    }
    __syncthreads();

    for (int kt = 0; kt < 36; ++kt) {
        const uint32_t* cur = sAb + (kt & 1) * 256;
        uint32_t* nxt = sAb + ((kt + 1) & 1) * 256;

        uint4 bq = *(const uint4*)(g_W1fragB + ((kt * 72 + ntg) * 32 + lane) * 4);

        if (kt < 35 && active) {
            nxt[sbase]     = pack_bf2(v.x, v.y);
            nxt[sbase + 4] = pack_bf2(v.z, v.w);
            if (kt < 34) v = *(const float4*)(srcp + (kt + 2) * 32);
        }

        const uint32_t* p = (const uint32_t*)&bq;
#pragma unroll
        for (int ks = 0; ks < 2; ++ks) {
            uint4 av = *(const uint4*)(cur + (ks * 32 + lane) * 4);
            const uint32_t* a = (const uint32_t*)&av;
            mma_bf16(acc, a, p[2 * ks], p[2 * ks + 1]);
        }
        __syncthreads();
    }

    const int cc = ntg * 8 + tig * 2;
    const float bv0 = b1[cc], bv1 = b1[cc + 1];
    {
        int r0 = m0 + gid, r1 = r0 + 8;
        float x;
        x = acc[0] + bv0; g_h1[(size_t)r0 * 576 + cc]     = x * normcdff(x);
        x = acc[1] + bv1; g_h1[(size_t)r0 * 576 + cc + 1] = x * normcdff(x);
        x = acc[2] + bv0; g_h1[(size_t)r1 * 576 + cc]     = x * normcdff(x);
        x = acc[3] + bv1; g_h1[(size_t)r1 * 576 + cc + 1] = x * normcdff(x);
    }
}

// ---------------------------------------------------------------------------
// logits: out = log_softmax(g_h1 @ W2 + b2)   grid 128, block 256
// ---------------------------------------------------------------------------
__global__ void logits_kernel(const float* __restrict__ W2, const float* __restrict__ b2,
                              float* __restrict__ out)
{
    __shared__ float sW2[1152];
    const int tid = threadIdx.x;
    const int lane = tid & 31, warp = tid >> 5;
    for (int j = tid; j < 1152; j += 256) sW2[j] = W2[j];
    __syncthreads();

    const int r = blockIdx.x * 8 + warp;
    float p0 = 0.f, p1 = 0.f;
    const float* hrow = g_h1 + (size_t)r * 576;
#pragma unroll
    for (int q = 0; q < 18; ++q) {
        int j = lane + 32 * q;
        float h = hrow[j];
        p0 += h * sW2[2 * j];
        p1 += h * sW2[2 * j + 1];
    }
#pragma unroll
    for (int o = 16; o > 0; o >>= 1) {
        p0 += __shfl_xor_sync(0xffffffffu, p0, o);
        p1 += __shfl_xor_sync(0xffffffffu, p1, o);
    }
    if (lane == 0) {
        float l0 = p0 + b2[0], l1 = p1 + b2[1];
        float m = fmaxf(l0, l1);
        float lse = m + logf(expf(l0 - m) + expf(l1 - m));
        out[(size_t)r * 2 + 0] = l0 - lse;
        out[(size_t)r * 2 + 1] = l1 - lse;
    }
}

// ---------------------------------------------------------------------------
extern "C" void kernel_launch(void* const* d_in, const int* in_sizes, int n_in,
                              void* d_out, int out_size)
{
    const float* pooled = (const float*)d_in[0];
    const float* x_coord= (const float*)d_in[1];
    const float* node1  = (const float*)d_in[2];
    const float* node2  = (const float*)d_in[3];
    const float* neigh1 = (const float*)d_in[4];
    const float* neigh2 = (const float*)d_in[5];
    const float* dist1  = (const float*)d_in[6];
    const float* dist2  = (const float*)d_in[7];
    const int*   len1   = (const int*)d_in[8];
    const int*   len2   = (const int*)d_in[9];
    const float* Ww  = (const float*)d_in[10];
    const float* bw  = (const float*)d_in[11];
    const float* Wa  = (const float*)d_in[12];
    const float* ba  = (const float*)d_in[13];
    const float* Wdb = (const float*)d_in[14];
    const float* bdb = (const float*)d_in[15];
    const float* Wn  = (const float*)d_in[16];
    const float* bn  = (const float*)d_in[17];
    const float* Wc  = (const float*)d_in[18];
    const float* bc  = (const float*)d_in[19];
    const float* W1  = (const float*)d_in[20];
    const float* b1  = (const float*)d_in[21];
    const float* W2  = (const float*)d_in[22];
    const float* b2  = (const float*)d_in[23];
    float* out = (float*)d_out;

    prep_kernel<<<1488, 256>>>(Ww, W1);

    side_kernel<<<296, 256>>>(node1, node2, neigh1, neigh2,
                              dist1, dist2, len1, len2,
                              bw, Wa, ba, Wdb, bdb);

    xbuild_kernel<<<BATCH / 4, 256>>>(Wn, bn, pooled, x_coord, Wc, bc);

    head_mm_kernel<<<dim3(64, 9), 256>>>(b1);

    logits_kernel<<<BATCH / 8, 256>>>(W2, b2, out);
}

// round 11
// speedup vs baseline: 1.1255x; 1.1255x over previous
#include <cuda_runtime.h>
#include <cuda_bf16.h>
#include <math.h>
#include <stdint.h>

#define BATCH 1024
#define NMAXN 100
#define HD    768

// ---------------- scratch (no allocations allowed) ----------------
__device__ float g_sim[BATCH * 256];
__device__ float g_h  [BATCH * 1152];
__device__ float g_h1 [BATCH * 576];
__device__ unsigned g_counter;
// Ww in bf16 fragment layout for m16n8k16: [kt(24)][nt(16)][lane(32)][reg(4)] (uint32 = bf16x2)
__device__ __align__(16) uint32_t g_WfragB[24 * 16 * 32 * 4];
// W1 in bf16 fragment layout for m16n8k16: [kt(36)][nt(72)][lane(32)][reg(4)]
__device__ __align__(16) uint32_t g_W1fragB[36 * 72 * 32 * 4];

__device__ __forceinline__ uint32_t pack_bf2(float lo, float hi) {
    __nv_bfloat162 p = __float22bfloat162_rn(make_float2(lo, hi));
    return *(uint32_t*)&p;
}
__device__ __forceinline__ void pref_l2(const void* p) {
    asm volatile("prefetch.global.L2 [%0];" :: "l"(p));
}

__device__ __forceinline__ void mma_bf16(float* c, const uint32_t* a, uint32_t b0, uint32_t b1) {
    asm volatile(
        "mma.sync.aligned.m16n8k16.row.col.f32.bf16.bf16.f32 "
        "{%0,%1,%2,%3}, {%4,%5,%6,%7}, {%8,%9}, {%0,%1,%2,%3};"
        : "+f"(c[0]), "+f"(c[1]), "+f"(c[2]), "+f"(c[3])
        : "r"(a[0]), "r"(a[1]), "r"(a[2]), "r"(a[3]), "r"(b0), "r"(b1));
}

// ---------------------------------------------------------------------------
// prep_kernel: counter reset + Ww bf16 frags + W1 bf16 frags in ONE launch
// ---------------------------------------------------------------------------
__global__ void prep_kernel(const float* __restrict__ Ww, const float* __restrict__ W1)
{
    if (blockIdx.x == 0 && threadIdx.x == 0) g_counter = 0u;
    if (blockIdx.x < 192) {
        int idx = blockIdx.x * 256 + threadIdx.x;      // 0..49151
        int r    = idx & 3;
        int lane = (idx >> 2) & 31;
        int nt   = (idx >> 7) & 15;
        int kt   = idx >> 11;
        int g = lane >> 2, tig = lane & 3;
        int n = nt * 8 + g;
        int k = kt * 32 + ((r >> 1) << 4) + ((r & 1) << 3) + 2 * tig;
        g_WfragB[idx] = pack_bf2(Ww[k * 128 + n], Ww[(k + 1) * 128 + n]);
    } else {
        int idx = (blockIdx.x - 192) * 256 + threadIdx.x;   // 0..331775
        int r    = idx & 3;
        int lane = (idx >> 2) & 31;
        int nt   = (idx >> 7) % 72;
        int kt   = idx / 9216;
        int g = lane >> 2, tig = lane & 3;
        int n = nt * 8 + g;
        int k = kt * 32 + ((r >> 1) << 4) + ((r & 1) << 3) + 2 * tig;
        g_W1fragB[idx] = pack_bf2(W1[k * 576 + n], W1[(k + 1) * 576 + n]);
    }
}

// ---------------------------------------------------------------------------
// side_kernel: persistent; per (b,side): bf16 MMA [node;neigh]@Ww, attention
// grid 296, block 256 (8 warps), dyn smem 71520 B   (R8 + 8-warp ctx split)
// ---------------------------------------------------------------------------
__global__ void __launch_bounds__(256, 2) side_kernel(
    const float* __restrict__ node1, const float* __restrict__ node2,
    const float* __restrict__ neigh1, const float* __restrict__ neigh2,
    const float* __restrict__ dist1, const float* __restrict__ dist2,
    const int* __restrict__ len1, const int* __restrict__ len2,
    const float* __restrict__ bw,
    const float* __restrict__ Wa, const float* __restrict__ ba,
    const float* __restrict__ Wdb, const float* __restrict__ bdb)
{
    extern __shared__ float sm[];
    uint32_t* sAb = (uint32_t*)sm;       // 2 x 1792 u32
    float* sWng = sm + 3584;             // 101 rows x stride 132 = 13332 (row0 = wn)
    float* sWa  = sWng + 13332;          // 256
    float* sBw  = sWa + 256;             // 128
    float* sDist= sBw + 128;             // 104
    float* sRaw = sDist + 104;           // 104
    float* sAtt = sRaw + 104;            // 104
    float* sC   = sAtt + 104;            // 8
    float* sDot = sC + 8;                // 2
    float* sPart= sDot + 2;              // 256
    __shared__ int sIdx;
    // 17878 floats -> 71520 B (rounded)

    const int tid  = threadIdx.x;
    const int warp = tid >> 5, lane = tid & 31;
    const int gid  = lane >> 2, tig = lane & 3;

    sWa[tid] = Wa[tid];
    if (tid < 128) sBw[tid] = bw[tid];
    __syncthreads();
    // one-time: dotbw0 = bw . Wa[0:128], dotbw1 = bw . Wa[128:256]
    if (warp == 0) {
        float s0 = 0.f, s1 = 0.f;
#pragma unroll
        for (int q = 0; q < 4; ++q) {
            s0 += sBw[lane + 32 * q] * sWa[lane + 32 * q];
            s1 += sBw[lane + 32 * q] * sWa[128 + lane + 32 * q];
        }
#pragma unroll
        for (int o = 16; o > 0; o >>= 1) {
            s0 += __shfl_xor_sync(0xffffffffu, s0, o);
            s1 += __shfl_xor_sync(0xffffffffu, s1, o);
        }
        if (lane == 0) { sDot[0] = s0; sDot[1] = s1; }
    }

    const float bav = ba[0], wdbv = Wdb[0], bdbv = bdb[0];

    while (true) {
        __syncthreads();
        if (tid == 0) sIdx = (int)atomicAdd(&g_counter, 1u);
        __syncthreads();
        const int item = sIdx;
        if (item >= 2 * BATCH) break;
        const int b = item >> 1, side = item & 1;

        const float* node  = side ? node2  : node1;
        const float* neigh = side ? neigh2 : neigh1;
        const float* dist  = side ? dist2  : dist1;
        int len = side ? len2[b] : len1[b];
        if (len < 1) len = 1; if (len > NMAXN) len = NMAXN;
        const int M = len + 1;
        const int mcount = (M + 15) >> 4;

        if (tid < NMAXN) { sDist[tid] = dist[(size_t)b * NMAXN + tid]; sRaw[tid] = 0.f; }
        if (tid == 128) sC[0] = 0.f;

        const float* nodeRow   = node  + (size_t)b * HD;
        const float* neighBase = neigh + (size_t)b * NMAXN * HD;

        // L2 prefetch of the whole item (neigh block is contiguous)
        {
            const char* pnb = (const char*)neighBase;
            const int pbytes = len * (HD * 4);
            for (int off = tid * 128; off < pbytes; off += 256 * 128) pref_l2(pnb + off);
            if (tid < 24) pref_l2((const char*)nodeRow + tid * 128);
        }

        int nact = 0;
        const float* srcp[4];
        int sbase[4];
#pragma unroll
        for (int i = 0; i < 4; ++i) {
            int f = tid + i * 256;
            if (f < M * 8) {
                int r = f >> 3, j = f & 7;
                int mt = r >> 4, r16 = r & 15, g8 = r16 & 7, hib = r16 >> 3;
                int ks = j >> 2, half = (j >> 1) & 1, tg = (j & 1) * 2;
                srcp[i]  = (r == 0 ? nodeRow : neighBase + (size_t)(r - 1) * HD) + j * 4;
                sbase[i] = ((mt * 2 + ks) * 32 + g8 * 4 + tg) * 4 + half * 2 + hib;
                nact = i + 1;
            }
        }

        float acc[7][2][4];
#pragma unroll
        for (int mt = 0; mt < 7; ++mt)
#pragma unroll
            for (int ni = 0; ni < 2; ++ni)
#pragma unroll
                for (int q = 0; q < 4; ++q) acc[mt][ni][q] = 0.f;

        // ---- prologue ----
        float4 v[4];
#pragma unroll
        for (int i = 0; i < 4; ++i) if (i < nact) v[i] = *(const float4*)(srcp[i]);

        uint4 bq0 = *(const uint4*)(g_WfragB + ((2 * warp)     * 32 + lane) * 4);
        uint4 bq1 = *(const uint4*)(g_WfragB + ((2 * warp + 1) * 32 + lane) * 4);

#pragma unroll
        for (int i = 0; i < 4; ++i) {
            if (i < nact) {
                sAb[sbase[i]]     = pack_bf2(v[i].x, v[i].y);
                sAb[sbase[i] + 4] = pack_bf2(v[i].z, v[i].w);
            }
        }
#pragma unroll
        for (int i = 0; i < 4; ++i)
            if (i < nact) v[i] = *(const float4*)(srcp[i] + 32);
        __syncthreads();

        // ---- mainloop: 1 barrier per k-tile ----
        for (int kt = 0; kt < 24; ++kt) {
            const uint32_t* cur = sAb + (kt & 1) * 1792;
            uint32_t* nxt = sAb + ((kt + 1) & 1) * 1792;

            uint4 nb0, nb1;
            if (kt < 23) {
                nb0 = *(const uint4*)(g_WfragB + (((kt + 1) * 16 + 2 * warp)     * 32 + lane) * 4);
                nb1 = *(const uint4*)(g_WfragB + (((kt + 1) * 16 + 2 * warp + 1) * 32 + lane) * 4);
#pragma unroll
                for (int i = 0; i < 4; ++i) {
                    if (i < nact) {
                        nxt[sbase[i]]     = pack_bf2(v[i].x, v[i].y);
                        nxt[sbase[i] + 4] = pack_bf2(v[i].z, v[i].w);
                    }
                }
                if (kt < 22) {
#pragma unroll
                    for (int i = 0; i < 4; ++i)
                        if (i < nact) v[i] = *(const float4*)(srcp[i] + (kt + 2) * 32);
                }
            }

            const uint32_t* p0 = (const uint32_t*)&bq0;
            const uint32_t* p1 = (const uint32_t*)&bq1;
#pragma unroll
            for (int ks = 0; ks < 2; ++ks) {
#pragma unroll
                for (int mt = 0; mt < 7; ++mt) {
                    if (mt >= mcount) break;
                    uint4 av = *(const uint4*)(cur + ((mt * 2 + ks) * 32 + lane) * 4);
                    const uint32_t* a = (const uint32_t*)&av;
                    mma_bf16(acc[mt][0], a, p0[2 * ks], p0[2 * ks + 1]);
                    mma_bf16(acc[mt][1], a, p1[2 * ks], p1[2 * ks + 1]);
                }
            }
            if (kt < 23) { bq0 = nb0; bq1 = nb1; }
            __syncthreads();
        }

        // epilogue: + bw -> sWng scatter, AND fused attention dots via atomics
#pragma unroll
        for (int mt = 0; mt < 7; ++mt) {
            if (mt >= mcount) break;
            int r0 = mt * 16 + gid, r1 = r0 + 8;
            float pr0 = 0.f, pr1 = 0.f;
#pragma unroll
            for (int ni = 0; ni < 2; ++ni) {
                int cc = (2 * warp + ni) * 8 + tig * 2;
                float wa0n = sWa[128 + cc], wa1n = sWa[128 + cc + 1];
                if (r0 < M) {
                    float2 o = { acc[mt][ni][0] + sBw[cc], acc[mt][ni][1] + sBw[cc + 1] };
                    *(float2*)(sWng + r0 * 132 + cc) = o;
                    if (r0 == 0)
                        pr0 += acc[mt][ni][0] * sWa[cc] + acc[mt][ni][1] * sWa[cc + 1];
                    else
                        pr0 += acc[mt][ni][0] * wa0n + acc[mt][ni][1] * wa1n;
                }
                if (r1 < M) {
                    float2 o = { acc[mt][ni][2] + sBw[cc], acc[mt][ni][3] + sBw[cc + 1] };
                    *(float2*)(sWng + r1 * 132 + cc) = o;
                    pr1 += acc[mt][ni][2] * wa0n + acc[mt][ni][3] * wa1n;
                }
            }
            pr0 += __shfl_xor_sync(0xffffffffu, pr0, 1);
            pr0 += __shfl_xor_sync(0xffffffffu, pr0, 2);
            pr1 += __shfl_xor_sync(0xffffffffu, pr1, 1);
            pr1 += __shfl_xor_sync(0xffffffffu, pr1, 2);
            if (tig == 0) {
                if (r0 < M) {
                    if (r0 == 0) atomicAdd(sC, pr0);
                    else         atomicAdd(&sRaw[r0 - 1], pr0);
                }
                if (r1 < M) atomicAdd(&sRaw[r1 - 1], pr1);
            }
        }
        __syncthreads();

        // warp 0: leaky_relu + dist bias, masked softmax
        if (warp == 0) {
            float cst = sC[0] + sDot[0] + sDot[1] + bav;
            float sc[4], ev[4];
            float mx = -3.4e38f;
#pragma unroll
            for (int q = 0; q < 4; ++q) {
                int n = lane + 32 * q;
                float vv = -3.4e38f;
                if (n < len) {
                    float x = cst + sRaw[n];
                    x = (x > 0.f) ? x : 0.01f * x;
                    vv = x + sDist[n] * wdbv + bdbv;
                }
                sc[q] = vv; mx = fmaxf(mx, vv);
            }
#pragma unroll
            for (int o = 16; o > 0; o >>= 1) mx = fmaxf(mx, __shfl_xor_sync(0xffffffffu, mx, o));
            float s = 0.f;
#pragma unroll
            for (int q = 0; q < 4; ++q) {
                int n = lane + 32 * q;
                float e = (n < len) ? expf(sc[q] - mx) : 0.f;
                ev[q] = e; s += e;
            }
#pragma unroll
            for (int o = 16; o > 0; o >>= 1) s += __shfl_xor_sync(0xffffffffu, s, o);
            float inv = 1.f / s;
#pragma unroll
            for (int q = 0; q < 4; ++q) {
                int n = lane + 32 * q;
                if (n < NMAXN) sAtt[n] = ev[q] * inv;
            }
        }
        __syncthreads();

        // ctx: split n-range across both thread halves (all 8 warps active)
        {
            const int col = tid & 127, half = tid >> 7;
            const int nmid = len >> 1;
            const int n0 = half ? nmid : 0;
            const int n1 = half ? len : nmid;
            float c0 = 0.f, c1 = 0.f;
            int n = n0;
            for (; n + 1 < n1; n += 2) {
                c0 += sAtt[n]     * sWng[(n + 1) * 132 + col];
                c1 += sAtt[n + 1] * sWng[(n + 2) * 132 + col];
            }
            if (n < n1) c0 += sAtt[n] * sWng[(n + 1) * 132 + col];
            sPart[tid] = c0 + c1;
        }
        __syncthreads();
        if (tid < 128) {
            float ctx = sPart[tid] + sPart[tid + 128];
            g_sim[(size_t)b * 256 + side * 128 + tid] = ctx * sWng[tid];
        }
    }
}

// ---------------------------------------------------------------------------
// xbuild: xneigh = relu([sim1,sim2]) @ Wn + bn -> g_h[:,896:1152],
// plus pooled/coord into g_h[:,0:896].  grid 256 (4 rows/block)
// ---------------------------------------------------------------------------
__global__ void __launch_bounds__(256) xbuild_kernel(
    const float* __restrict__ Wn, const float* __restrict__ bn,
    const float* __restrict__ pooled, const float* __restrict__ x_coord,
    const float* __restrict__ Wc, const float* __restrict__ bc)
{
    __shared__ float sS[4 * 256];
    const int b0 = blockIdx.x * 4;
    const int tid = threadIdx.x;
#pragma unroll
    for (int r = 0; r < 4; ++r)
        sS[r * 256 + tid] = fmaxf(g_sim[(size_t)(b0 + r) * 256 + tid], 0.f);
    __syncthreads();
    float acc[4];
    const float bnv = bn[tid];
#pragma unroll
    for (int r = 0; r < 4; ++r) acc[r] = bnv;
    for (int k0 = 0; k0 < 256; k0 += 4) {
        float w0 = Wn[(k0 + 0) * 256 + tid];
        float w1 = Wn[(k0 + 1) * 256 + tid];
        float w2 = Wn[(k0 + 2) * 256 + tid];
        float w3 = Wn[(k0 + 3) * 256 + tid];
#pragma unroll
        for (int r = 0; r < 4; ++r) {
            acc[r] += sS[r * 256 + k0] * w0;
            acc[r] += sS[r * 256 + k0 + 1] * w1;
            acc[r] += sS[r * 256 + k0 + 2] * w2;
            acc[r] += sS[r * 256 + k0 + 3] * w3;
        }
    }
#pragma unroll
    for (int r = 0; r < 4; ++r) {
        int b = b0 + r;
        g_h[(size_t)b * 1152 + 896 + tid] = acc[r];
#pragma unroll
        for (int p = 0; p < 3; ++p)
            g_h[(size_t)b * 1152 + p * 256 + tid] = pooled[(size_t)b * 768 + p * 256 + tid];
        if (tid < 128) {
            g_h[(size_t)b * 1152 + 768 + tid] = x_coord[b] * Wc[tid] + bc[tid];
        }
    }
}

// ---------------------------------------------------------------------------
// head_mm: g_h1 = gelu(g_h @ W1 + b1)  bf16, grid (64,9) = 16x64 tiles
// 4-buffer ring, 2 k-tiles per barrier (18 barriers)
// ---------------------------------------------------------------------------
__global__ void __launch_bounds__(256) head_mm_kernel(const float* __restrict__ b1)
{
    __shared__ uint32_t sAb[4 * 256];   // 4 buffers x [ks(2)][lane(32)][reg(4)]... per kt

    const int tid  = threadIdx.x;
    const int warp = tid >> 5, lane = tid & 31;
    const int gid  = lane >> 2, tig = lane & 3;
    const int m0   = blockIdx.x * 16;
    const int ntg  = blockIdx.y * 8 + warp;

    {
        const char* ph = (const char*)(g_h + (size_t)m0 * 1152);
        for (int off = tid * 128; off < 16 * 1152 * 4; off += 256 * 128) pref_l2(ph + off);
    }

    const bool active = tid < 128;
    const float* srcp = g_h;
    int sbase = 0;
    if (active) {
        int r = tid >> 3, j = tid & 7;
        int g8 = (r & 15) & 7, hib = (r & 15) >> 3;
        int ks = j >> 2, half = (j >> 1) & 1, tg = (j & 1) * 2;
        srcp  = g_h + (size_t)(m0 + r) * 1152 + j * 4;
        sbase = (ks * 32 + g8 * 4 + tg) * 4 + half * 2 + hib;
    }

    float acc[4];
#pragma unroll
    for (int q = 0; q < 4; ++q) acc[q] = 0.f;

    float4 va = make_float4(0.f, 0.f, 0.f, 0.f);
    float4 vb = va;
    if (active) {
        va = *(const float4*)(srcp);            // kt 0
        vb = *(const float4*)(srcp + 32);       // kt 1
        sAb[sbase]           = pack_bf2(va.x, va.y);
        sAb[sbase + 4]       = pack_bf2(va.z, va.w);
        sAb[256 + sbase]     = pack_bf2(vb.x, vb.y);
        sAb[256 + sbase + 4] = pack_bf2(vb.z, vb.w);
        va = *(const float4*)(srcp + 64);       // kt 2
        vb = *(const float4*)(srcp + 96);       // kt 3
    }
    __syncthreads();

    for (int it = 0; it < 18; ++it) {
        const int kt = 2 * it;
        const uint32_t* cur0 = sAb + ((kt)     & 3) * 256;
        const uint32_t* cur1 = sAb + ((kt + 1) & 3) * 256;

        uint4 bqa = *(const uint4*)(g_W1fragB + (((kt)     * 72 + ntg) * 32 + lane) * 4);
        uint4 bqb = *(const uint4*)(g_W1fragB + (((kt + 1) * 72 + ntg) * 32 + lane) * 4);

        if (it < 17 && active) {
            uint32_t* n0 = sAb + ((kt + 2) & 3) * 256;
            uint32_t* n1 = sAb + ((kt + 3) & 3) * 256;
            n0[sbase]     = pack_bf2(va.x, va.y);
            n0[sbase + 4] = pack_bf2(va.z, va.w);
            n1[sbase]     = pack_bf2(vb.x, vb.y);
            n1[sbase + 4] = pack_bf2(vb.z, vb.w);
            if (it < 16) {
                va = *(const float4*)(srcp + (kt + 4) * 32);
                vb = *(const float4*)(srcp + (kt + 5) * 32);
            }
        }

        const uint32_t* pa = (const uint32_t*)&bqa;
        const uint32_t* pb = (const uint32_t*)&bqb;
#pragma unroll
        for (int ks = 0; ks < 2; ++ks) {
            uint4 av0 = *(const uint4*)(cur0 + (ks * 32 + lane) * 4);
            mma_bf16(acc, (const uint32_t*)&av0, pa[2 * ks], pa[2 * ks + 1]);
        }
#pragma unroll
        for (int ks = 0; ks < 2; ++ks) {
            uint4 av1 = *(const uint4*)(cur1 + (ks * 32 + lane) * 4);
            mma_bf16(acc, (const uint32_t*)&av1, pb[2 * ks], pb[2 * ks + 1]);
        }
        __syncthreads();
    }

    const int cc = ntg * 8 + tig * 2;
    const float bv0 = b1[cc], bv1 = b1[cc + 1];
    {
        int r0 = m0 + gid, r1 = r0 + 8;
        float x;
        x = acc[0] + bv0; g_h1[(size_t)r0 * 576 + cc]     = x * normcdff(x);
        x = acc[1] + bv1; g_h1[(size_t)r0 * 576 + cc + 1] = x * normcdff(x);
        x = acc[2] + bv0; g_h1[(size_t)r1 * 576 + cc]     = x * normcdff(x);
        x = acc[3] + bv1; g_h1[(size_t)r1 * 576 + cc + 1] = x * normcdff(x);
    }
}

// ---------------------------------------------------------------------------
// logits: out = log_softmax(g_h1 @ W2 + b2)   grid 128, block 256
// ---------------------------------------------------------------------------
__global__ void logits_kernel(const float* __restrict__ W2, const float* __restrict__ b2,
                              float* __restrict__ out)
{
    __shared__ float sW2[1152];
    const int tid = threadIdx.x;
    const int lane = tid & 31, warp = tid >> 5;
    for (int j = tid; j < 1152; j += 256) sW2[j] = W2[j];
    __syncthreads();

    const int r = blockIdx.x * 8 + warp;
    float p0 = 0.f, p1 = 0.f;
    const float* hrow = g_h1 + (size_t)r * 576;
#pragma unroll
    for (int q = 0; q < 18; ++q) {
        int j = lane + 32 * q;
        float h = hrow[j];
        p0 += h * sW2[2 * j];
        p1 += h * sW2[2 * j + 1];
    }
#pragma unroll
    for (int o = 16; o > 0; o >>= 1) {
        p0 += __shfl_xor_sync(0xffffffffu, p0, o);
        p1 += __shfl_xor_sync(0xffffffffu, p1, o);
    }
    if (lane == 0) {
        float l0 = p0 + b2[0], l1 = p1 + b2[1];
        float m = fmaxf(l0, l1);
        float lse = m + logf(expf(l0 - m) + expf(l1 - m));
        out[(size_t)r * 2 + 0] = l0 - lse;
        out[(size_t)r * 2 + 1] = l1 - lse;
    }
}

// ---------------------------------------------------------------------------
extern "C" void kernel_launch(void* const* d_in, const int* in_sizes, int n_in,
                              void* d_out, int out_size)
{
    const float* pooled = (const float*)d_in[0];
    const float* x_coord= (const float*)d_in[1];
    const float* node1  = (const float*)d_in[2];
    const float* node2  = (const float*)d_in[3];
    const float* neigh1 = (const float*)d_in[4];
    const float* neigh2 = (const float*)d_in[5];
    const float* dist1  = (const float*)d_in[6];
    const float* dist2  = (const float*)d_in[7];
    const int*   len1   = (const int*)d_in[8];
    const int*   len2   = (const int*)d_in[9];
    const float* Ww  = (const float*)d_in[10];
    const float* bw  = (const float*)d_in[11];
    const float* Wa  = (const float*)d_in[12];
    const float* ba  = (const float*)d_in[13];
    const float* Wdb = (const float*)d_in[14];
    const float* bdb = (const float*)d_in[15];
    const float* Wn  = (const float*)d_in[16];
    const float* bn  = (const float*)d_in[17];
    const float* Wc  = (const float*)d_in[18];
    const float* bc  = (const float*)d_in[19];
    const float* W1  = (const float*)d_in[20];
    const float* b1  = (const float*)d_in[21];
    const float* W2  = (const float*)d_in[22];
    const float* b2  = (const float*)d_in[23];
    float* out = (float*)d_out;

    prep_kernel<<<1488, 256>>>(Ww, W1);

    const int smB = 17880 * (int)sizeof(float);   // 71520 B
    cudaFuncSetAttribute(side_kernel, cudaFuncAttributeMaxDynamicSharedMemorySize, smB);
    side_kernel<<<296, 256, smB>>>(node1, node2, neigh1, neigh2,
                                   dist1, dist2, len1, len2,
                                   bw, Wa, ba, Wdb, bdb);

    xbuild_kernel<<<BATCH / 4, 256>>>(Wn, bn, pooled, x_coord, Wc, bc);

    head_mm_kernel<<<dim3(64, 9), 256>>>(b1);

    logits_kernel<<<BATCH / 8, 256>>>(W2, b2, out);
}